// round 14
// baseline (speedup 1.0000x reference)
#include <cuda_runtime.h>
#include <cuda.h>

#define NS      32768
#define NT      512
#define SEASK   24
#define LEVW    512
#define SEAW    536
#define LOGW    511

#define NWARP   32          // series per block
#define BLOCK   128         // W0/W1 ping-pong compute, W2 IO-lo, W3 IO-hi+TMA
#define NPER    21          // periods of 24 steps, t = 8..511
#define YSTR    28          // y smem row stride (conflict-free .128)
#define TSTR    24          // TMA tile row stride (packed)
#define DSTR    28          // dtile row stride

__device__ __forceinline__ unsigned smem_u32(const void* p) {
    return (unsigned)__cvta_generic_to_shared(p);
}
__device__ __forceinline__ void cp16(unsigned dst, const void* src) {
    asm volatile("cp.async.cg.shared.global [%0], [%1], 16;\n" :: "r"(dst), "l"(src) : "memory");
}
__device__ __forceinline__ void cp_commit() {
    asm volatile("cp.async.commit_group;\n" ::: "memory");
}
template<int N> __device__ __forceinline__ void cp_wait() {
    asm volatile("cp.async.wait_group %0;\n" :: "n"(N) : "memory");
}
__device__ __forceinline__ void tma_store2d(const void* map, int x, int y, unsigned smem) {
    asm volatile("cp.async.bulk.tensor.2d.global.shared::cta.tile.bulk_group [%0, {%1, %2}], [%3];"
                 :: "l"(map), "r"(x), "r"(y), "r"(smem) : "memory");
}
__device__ __forceinline__ void bulk_commit() {
    asm volatile("cp.async.bulk.commit_group;" ::: "memory");
}
template<int N> __device__ __forceinline__ void bulk_wait() {
    asm volatile("cp.async.bulk.wait_group %0;" :: "n"(N) : "memory");
}
__device__ __forceinline__ void fence_async_shared() {
    asm volatile("fence.proxy.async.shared::cta;" ::: "memory");
}

// 12 recurrence steps. sold column k = seasonal value of slot (8+k)%24 as of
// the previous period (exactly 24 steps before its use -> matches reference).
__device__ __forceinline__ void half12(
    const float* __restrict__ ysm, const float* __restrict__ sold,
    float* __restrict__ lnew, float* __restrict__ snew,
    float a, float oma, float& lev)
{
    float yt[12], sv[12], q_[12], nl_[12];
    #pragma unroll
    for (int m = 0; m < 3; m++) {
        const float4 v = *(const float4*)(ysm  + 4 * m);
        const float4 w = *(const float4*)(sold + 4 * m);
        yt[4*m+0] = v.x; yt[4*m+1] = v.y; yt[4*m+2] = v.z; yt[4*m+3] = v.w;
        sv[4*m+0] = w.x; sv[4*m+1] = w.y; sv[4*m+2] = w.z; sv[4*m+3] = w.w;
    }
    #pragma unroll
    for (int k = 0; k < 12; k++) q_[k] = a * __fdividef(yt[k], sv[k]);
    #pragma unroll
    for (int k = 0; k < 12; k++) { nl_[k] = fmaf(oma, lev, q_[k]); lev = nl_[k]; }
    #pragma unroll
    for (int m = 0; m < 3; m++) {
        const float n0 = fmaf(a, __fdividef(yt[4*m+0], nl_[4*m+0]), oma * sv[4*m+0]);
        const float n1 = fmaf(a, __fdividef(yt[4*m+1], nl_[4*m+1]), oma * sv[4*m+1]);
        const float n2 = fmaf(a, __fdividef(yt[4*m+2], nl_[4*m+2]), oma * sv[4*m+2]);
        const float n3 = fmaf(a, __fdividef(yt[4*m+3], nl_[4*m+3]), oma * sv[4*m+3]);
        *(float4*)(snew + 4*m) = make_float4(n0, n1, n2, n3);
        *(float4*)(lnew + 4*m) = make_float4(nl_[4*m+0], nl_[4*m+1], nl_[4*m+2], nl_[4*m+3]);
    }
}

// 12 logs + diffs (cols [c0, c0+12) of a period); returns last log.
__device__ __forceinline__ float loghalf(const float* __restrict__ nlrow,
                                         float* __restrict__ drow, float llev)
{
    #pragma unroll
    for (int m = 0; m < 3; m++) {
        const float4 v = *(const float4*)(nlrow + 4 * m);
        const float l0 = __logf(v.x), l1 = __logf(v.y);
        const float l2 = __logf(v.z), l3 = __logf(v.w);
        *(float4*)(drow + 4 * m) = make_float4(l0 - llev, l1 - l0, l2 - l1, l3 - l2);
        llev = l3;
    }
    return llev;
}

__global__ __launch_bounds__(BLOCK, 6) void es_fwd_kernel(
    const __grid_constant__ CUtensorMap tml,
    const __grid_constant__ CUtensorMap tms,
    const float* __restrict__ y,
    const int*   __restrict__ idxs,
    const float* __restrict__ lev_sms_p,
    const float* __restrict__ init_seas_p,
    float* __restrict__ out)
{
    __shared__ __align__(16) float ybufW[2][NWARP * YSTR];  // per-compute-warp y staging
    __shared__ __align__(16) float y0buf[NWARP * 12];       // peel y
    __shared__ __align__(16) float ltile[3][NWARP * TSTR];  // levels (TMA src + log src)
    __shared__ __align__(16) float stile[3][NWARP * TSTR];  // seas (TMA src + state carry)
    __shared__ __align__(16) float dtile[NWARP * DSTR];     // gd staging (W2 lo / W3 hi)
    __shared__ float levb[2][NWARP];
    __shared__ float llevb[NWARP];

    const int tid  = threadIdx.x;
    const int wid  = tid >> 5;
    const int lane = tid & 31;
    const int s0   = blockIdx.x * NWARP;
    const int s    = s0 + lane;

    float* gl = out;
    float* gs = out + (size_t)NS * LEVW;
    float* gd = gs  + (size_t)NS * SEAW;

    const char* ybase = (const char*)(y + (size_t)s0 * NT);
    const int idx = idxs[s];
    // reference derives BOTH smoothing params from lev_sms (its own quirk)
    const float a   = 1.0f / (1.0f + __expf(-lev_sms_p[idx]));
    const float oma = 1.0f - a;
    const float* isr = init_seas_p + (size_t)idx * SEASK;

    float sv_[8], rsv0 = 0.0f;   // W0 peel state

    // ======================= INIT =======================
    if (wid == 0) {
        // my y groups: peel y + period-0 y (one group; I wait on it at iter 0)
        #pragma unroll
        for (int j = 0; j < 2; j++) {
            const int f = lane + 32 * j;
            const int row = f >> 1, col = f & 1;
            cp16(smem_u32(y0buf) + row * 48 + col * 16, ybase + row * (NT * 4) + col * 16);
        }
        #pragma unroll
        for (int j = 0; j < 6; j++) {
            const int f = lane + 32 * j;
            const int row = f / 6, col = f % 6;
            cp16(smem_u32(ybufW[0]) + row * (YSTR * 4) + col * 16,
                 ybase + 32 + row * (NT * 4) + col * 16);
        }
        cp_commit();
        // peel seasonal state (pos 0..7); emit gs cols 0..7
        const float4 x0 = *(const float4*)(isr + 0);
        const float4 x1 = *(const float4*)(isr + 4);
        float4 e0, e1;
        e0.x = __expf(x0.x); e0.y = __expf(x0.y); e0.z = __expf(x0.z); e0.w = __expf(x0.w);
        e1.x = __expf(x1.x); e1.y = __expf(x1.y); e1.z = __expf(x1.z); e1.w = __expf(x1.w);
        sv_[0]=e0.x; sv_[1]=e0.y; sv_[2]=e0.z; sv_[3]=e0.w;
        sv_[4]=e1.x; sv_[5]=e1.y; sv_[6]=e1.z; sv_[7]=e1.w;
        rsv0 = __expf(-x0.x);
        float4* gsr = (float4*)(gs + (size_t)s * SEAW);
        __stcs(gsr + 0, e0); __stcs(gsr + 1, e1);
    } else if (wid == 1) {
        // my y group: period-1 y (I wait on it at iter 1)
        #pragma unroll
        for (int j = 0; j < 6; j++) {
            const int f = lane + 32 * j;
            const int row = f / 6, col = f % 6;
            cp16(smem_u32(ybufW[1]) + row * (YSTR * 4) + col * 16,
                 ybase + 32 + 96 + row * (NT * 4) + col * 16);
        }
        cp_commit();
    } else {
        // W2: pos 8..15 -> seed stile[2] cols 0..7, gs cols 8..15
        // W3: pos 16..23 -> seed stile[2] cols 8..15, gs cols 16..23
        const int base = (wid == 2) ? 8 : 16;
        const float4 x0 = *(const float4*)(isr + base);
        const float4 x1 = *(const float4*)(isr + base + 4);
        float4 e0, e1;
        e0.x = __expf(x0.x); e0.y = __expf(x0.y); e0.z = __expf(x0.z); e0.w = __expf(x0.w);
        e1.x = __expf(x1.x); e1.y = __expf(x1.y); e1.z = __expf(x1.z); e1.w = __expf(x1.w);
        float4* gsr = (float4*)(gs + (size_t)s * SEAW + base);
        __stcs(gsr + 0, e0); __stcs(gsr + 1, e1);
        float* sd = stile[2] + lane * TSTR + (base - 8);
        *(float4*)(sd) = e0; *(float4*)(sd + 4) = e1;
    }
    __syncthreads();   // B_init

    float lev = 0.0f;

    // iter p: owner warp (p&1) computes period p; W2/W3 do IO for period p-1;
    // the non-owner compute warp prefetches its next y.
    #pragma unroll 1
    for (int iter = 0; iter <= NPER; iter++) {
        if (wid < 2) {
            const bool own = (iter < NPER) && ((iter & 1) == wid);
            if (own) {
                cp_wait<0>();     // my y group (committed >= 1 iteration ago)
                __syncwarp();

                if (iter == 0) {
                    // ---- peel steps 0..7 ----
                    const float4 v0 = *(const float4*)(y0buf + lane * 12);
                    const float4 v1 = *(const float4*)(y0buf + lane * 12 + 4);
                    float yt[8] = {v0.x, v0.y, v0.z, v0.w, v1.x, v1.y, v1.z, v1.w};
                    float q_[8], nl_[8], dt_[8], ns_[8];

                    lev = yt[0] * rsv0;
                    float llev = __logf(lev);
                    nl_[0] = lev; dt_[0] = 0.0f;
                    #pragma unroll
                    for (int k = 1; k < 8; k++) q_[k] = a * __fdividef(yt[k], sv_[k]);
                    #pragma unroll
                    for (int k = 1; k < 8; k++) { nl_[k] = fmaf(oma, lev, q_[k]); lev = nl_[k]; }
                    #pragma unroll
                    for (int k = 1; k < 8; k++)
                        ns_[k] = fmaf(a, __fdividef(yt[k], nl_[k]), oma * sv_[k]);
                    #pragma unroll
                    for (int k = 1; k < 8; k++) {
                        const float ll = __logf(nl_[k]);
                        dt_[k] = ll - llev; llev = ll;
                    }
                    llevb[lane] = llev;     // col -1 carry for W2's period 0

                    // seed stile[2] cols 16..23 (slot 0 = init, slots 1..7 = peel)
                    float* sd = stile[2] + lane * TSTR + 16;
                    *(float4*)(sd)     = make_float4(sv_[0], ns_[1], ns_[2], ns_[3]);
                    *(float4*)(sd + 4) = make_float4(ns_[4], ns_[5], ns_[6], ns_[7]);

                    // peel writeback via dtile scratch (l:0-7, s:8-15, d:16-23)
                    float* pb = dtile + lane * DSTR;
                    *(float4*)(pb +  0) = make_float4(nl_[0], nl_[1], nl_[2], nl_[3]);
                    *(float4*)(pb +  4) = make_float4(nl_[4], nl_[5], nl_[6], nl_[7]);
                    *(float4*)(pb +  8) = make_float4(sv_[0], ns_[1], ns_[2], ns_[3]);
                    *(float4*)(pb + 12) = make_float4(ns_[4], ns_[5], ns_[6], ns_[7]);
                    *(float4*)(pb + 16) = make_float4(dt_[0], dt_[1], dt_[2], dt_[3]);
                    *(float4*)(pb + 20) = make_float4(dt_[4], dt_[5], dt_[6], dt_[7]);
                    __syncwarp();
                    #pragma unroll
                    for (int j = 0; j < 2; j++) {
                        const int f = lane + 32 * j;
                        const int row = f >> 1, qd = f & 1;
                        __stcs((float4*)(gl + (size_t)(s0 + row) * LEVW) + qd,
                               ((const float4*)(dtile + row * DSTR))[qd]);
                        __stcs((float4*)(gs + (size_t)(s0 + row) * SEAW + SEASK) + qd,
                               ((const float4*)(dtile + row * DSTR + 8))[qd]);
                    }
                    #pragma unroll
                    for (int j = 0; j < 7; j++) {
                        const int i = lane + 32 * j;
                        const int row = i / 7, k = i % 7;
                        __stcs(gd + (size_t)(s0 + row) * LOGW + k, dtile[row * DSTR + 17 + k]);
                    }
                    __syncwarp();
                } else {
                    lev = levb[(iter - 1) & 1][lane];   // carry from peer
                }

                // ---- compute period `iter` ----
                const int bw = iter % 3;
                const int br = (iter + 2) % 3;          // previous period's buffer
                const float* ysm  = ybufW[wid] + lane * YSTR;
                const float* sold = stile[br] + lane * TSTR;
                float* lnew = ltile[bw] + lane * TSTR;
                float* snew = stile[bw] + lane * TSTR;
                half12(ysm,      sold,      lnew,      snew,      a, oma, lev);
                half12(ysm + 12, sold + 12, lnew + 12, snew + 12, a, oma, lev);
                levb[iter & 1][lane] = lev;
            } else if (iter < NPER) {
                // off iteration: prefetch y for my next compute period (iter+1)
                const int pn = iter + 1;
                if (pn < NPER) {
                    const char* yb = ybase + 32 + (size_t)pn * 96;
                    const unsigned d = smem_u32(ybufW[wid]);
                    #pragma unroll
                    for (int j = 0; j < 6; j++) {
                        const int f = lane + 32 * j;
                        const int row = f / 6, col = f % 6;
                        cp16(d + row * (YSTR * 4) + col * 16, yb + row * (NT * 4) + col * 16);
                    }
                    cp_commit();
                }
            }
        } else if (iter >= 1) {
            const int P  = iter - 1;
            const int b  = P % 3;
            const int tp = 8 + 24 * P;
            const float* nlrow = ltile[b] + lane * TSTR;
            float* db = dtile + lane * DSTR;

            if (wid == 2) {
                // cols 0..11
                const float llev = llevb[lane];      // col 23 of P-1 (or peel)
                loghalf(nlrow, db, llev);
                __syncwarp();
                #pragma unroll
                for (int j = 0; j < 12; j++) {
                    const int i = lane + 32 * j;
                    const int row = i / 12, k = i % 12;
                    __stcs(gd + (size_t)(s0 + row) * LOGW + tp - 1 + k, dtile[row * DSTR + k]);
                }
            } else {
                // W3: TMA for period P + cols 12..23
                if (lane == 0) {
                    fence_async_shared();
                    tma_store2d(&tml, tp,         s0, smem_u32(ltile[b]));
                    tma_store2d(&tms, tp + SEASK, s0, smem_u32(stile[b]));
                    bulk_commit();
                }
                const float base = __logf(nlrow[11]);      // boundary (redundant)
                const float llast = loghalf(nlrow + 12, db + 12, base);
                llevb[lane] = llast;                       // col -1 for period P+1
                __syncwarp();
                #pragma unroll
                for (int j = 0; j < 12; j++) {
                    const int i = lane + 32 * j;
                    const int row = i / 12, k = 12 + i % 12;
                    __stcs(gd + (size_t)(s0 + row) * LOGW + tp - 1 + k, dtile[row * DSTR + k]);
                }
                // drain groups <= P-1: their buffers ((P-1)%3) are rewritten by
                // compute(P+2) only after the NEXT barrier -> safe
                if (lane == 0) bulk_wait<1>();
            }
        }
        __syncthreads();
    }

    if (wid == 3 && lane == 0) bulk_wait<0>();   // smem must outlive pending TMA
}

extern "C" void kernel_launch(void* const* d_in, const int* in_sizes, int n_in,
                              void* d_out, int out_size)
{
    const float* y         = (const float*)d_in[0];
    const int*   idxs      = (const int*)  d_in[1];
    const float* lev_sms   = (const float*)d_in[2];
    const float* init_seas = (const float*)d_in[4];  // d_in[3] unused (reference quirk)
    float* out = (float*)d_out;

    typedef CUresult (*EncodeFn)(CUtensorMap*, CUtensorMapDataType, cuuint32_t, void*,
                                 const cuuint64_t*, const cuuint64_t*, const cuuint32_t*,
                                 const cuuint32_t*, CUtensorMapInterleave, CUtensorMapSwizzle,
                                 CUtensorMapL2promotion, CUtensorMapFloatOOBfill);
    EncodeFn enc = nullptr;
    cudaDriverEntryPointQueryResult qr;
    cudaGetDriverEntryPointByVersion("cuTensorMapEncodeTiled", (void**)&enc, 12000,
                                     cudaEnableDefault, &qr);

    CUtensorMap tml, tms;
    {
        cuuint64_t dims[2]    = { (cuuint64_t)LEVW, (cuuint64_t)NS };
        cuuint64_t strides[1] = { (cuuint64_t)LEVW * 4 };
        cuuint32_t box[2]     = { 24, 32 };
        cuuint32_t es[2]      = { 1, 1 };
        enc(&tml, CU_TENSOR_MAP_DATA_TYPE_FLOAT32, 2, out, dims, strides, box, es,
            CU_TENSOR_MAP_INTERLEAVE_NONE, CU_TENSOR_MAP_SWIZZLE_NONE,
            CU_TENSOR_MAP_L2_PROMOTION_L2_128B, CU_TENSOR_MAP_FLOAT_OOB_FILL_NONE);
    }
    {
        float* gsp = out + (size_t)NS * LEVW;
        cuuint64_t dims[2]    = { (cuuint64_t)SEAW, (cuuint64_t)NS };
        cuuint64_t strides[1] = { (cuuint64_t)SEAW * 4 };
        cuuint32_t box[2]     = { 24, 32 };
        cuuint32_t es[2]      = { 1, 1 };
        enc(&tms, CU_TENSOR_MAP_DATA_TYPE_FLOAT32, 2, gsp, dims, strides, box, es,
            CU_TENSOR_MAP_INTERLEAVE_NONE, CU_TENSOR_MAP_SWIZZLE_NONE,
            CU_TENSOR_MAP_L2_PROMOTION_L2_128B, CU_TENSOR_MAP_FLOAT_OOB_FILL_NONE);
    }

    es_fwd_kernel<<<NS / NWARP, BLOCK>>>(tml, tms, y, idxs, lev_sms, init_seas, out);
}

// round 15
// speedup vs baseline: 1.2031x; 1.2031x over previous
#include <cuda_runtime.h>
#include <cuda.h>

#define NS      32768
#define NT      512
#define SEASK   24
#define LEVW    512
#define SEAW    536
#define LOGW    511

#define NSER    64          // series per block (2 per thread-lane)
#define BLOCK   64          // W0 compute (32 lanes x 2 series), W1 IO
#define NPER    21          // periods of 24 steps, t = 8..511
#define YSTR    28          // y smem row stride
#define TSTR    24          // tile row stride (TMA packed)
#define DSTR    28          // dtile row stride

__device__ __forceinline__ unsigned smem_u32(const void* p) {
    return (unsigned)__cvta_generic_to_shared(p);
}
__device__ __forceinline__ void cp16(unsigned dst, const void* src) {
    asm volatile("cp.async.cg.shared.global [%0], [%1], 16;\n" :: "r"(dst), "l"(src) : "memory");
}
__device__ __forceinline__ void cp_commit() {
    asm volatile("cp.async.commit_group;\n" ::: "memory");
}
template<int N> __device__ __forceinline__ void cp_wait() {
    asm volatile("cp.async.wait_group %0;\n" :: "n"(N) : "memory");
}
__device__ __forceinline__ void tma_store2d(const void* map, int x, int y, unsigned smem) {
    asm volatile("cp.async.bulk.tensor.2d.global.shared::cta.tile.bulk_group [%0, {%1, %2}], [%3];"
                 :: "l"(map), "r"(x), "r"(y), "r"(smem) : "memory");
}
__device__ __forceinline__ void bulk_commit() {
    asm volatile("cp.async.bulk.commit_group;" ::: "memory");
}
template<int N> __device__ __forceinline__ void bulk_wait() {
    asm volatile("cp.async.bulk.wait_group %0;" :: "n"(N) : "memory");
}
__device__ __forceinline__ void fence_async_shared() {
    asm volatile("fence.proxy.async.shared::cta;" ::: "memory");
}

// 12 recurrence steps for one series. sold col k = seasonal value of slot
// (8+k)%24 as of the previous period (exactly 24 steps old -> matches ref).
__device__ __forceinline__ void half12(
    const float* __restrict__ ysm, const float* __restrict__ sold,
    float* __restrict__ lnew, float* __restrict__ snew,
    float a, float oma, float& lev)
{
    float yt[12], sv[12], q_[12], nl_[12];
    #pragma unroll
    for (int m = 0; m < 3; m++) {
        const float4 v = *(const float4*)(ysm  + 4 * m);
        const float4 w = *(const float4*)(sold + 4 * m);
        yt[4*m+0] = v.x; yt[4*m+1] = v.y; yt[4*m+2] = v.z; yt[4*m+3] = v.w;
        sv[4*m+0] = w.x; sv[4*m+1] = w.y; sv[4*m+2] = w.z; sv[4*m+3] = w.w;
    }
    #pragma unroll
    for (int k = 0; k < 12; k++) q_[k] = a * __fdividef(yt[k], sv[k]);
    #pragma unroll
    for (int k = 0; k < 12; k++) { nl_[k] = fmaf(oma, lev, q_[k]); lev = nl_[k]; }
    #pragma unroll
    for (int m = 0; m < 3; m++) {
        const float n0 = fmaf(a, __fdividef(yt[4*m+0], nl_[4*m+0]), oma * sv[4*m+0]);
        const float n1 = fmaf(a, __fdividef(yt[4*m+1], nl_[4*m+1]), oma * sv[4*m+1]);
        const float n2 = fmaf(a, __fdividef(yt[4*m+2], nl_[4*m+2]), oma * sv[4*m+2]);
        const float n3 = fmaf(a, __fdividef(yt[4*m+3], nl_[4*m+3]), oma * sv[4*m+3]);
        *(float4*)(snew + 4*m) = make_float4(n0, n1, n2, n3);
        *(float4*)(lnew + 4*m) = make_float4(nl_[4*m+0], nl_[4*m+1], nl_[4*m+2], nl_[4*m+3]);
    }
}

__global__ __launch_bounds__(BLOCK) void es_fwd_kernel(
    const __grid_constant__ CUtensorMap tml,
    const __grid_constant__ CUtensorMap tms,
    const float* __restrict__ y,
    const int*   __restrict__ idxs,
    const float* __restrict__ lev_sms_p,
    const float* __restrict__ init_seas_p,
    float* __restrict__ out)
{
    __shared__ __align__(16) float ybuf[2][NSER * YSTR];   // 14336
    __shared__ __align__(16) float ltile[2][NSER * TSTR];  // 12288
    __shared__ __align__(16) float stile[2][NSER * TSTR];  // 12288 (also state carry)
    __shared__ __align__(16) float dtile[NSER * DSTR];     // 7168
    __shared__ float llevb[NSER];

    const int tid  = threadIdx.x;
    const int wid  = tid >> 5;
    const int lane = tid & 31;
    const int s0   = blockIdx.x * NSER;

    float* gl = out;
    float* gs = out + (size_t)NS * LEVW;
    float* gd = gs  + (size_t)NS * SEAW;
    const char* ybase = (const char*)(y + (size_t)s0 * NT);

    float aA, omaA, levA = 0.0f;
    float bA_sv[8], bA_r0 = 0.0f;
    float aB, omaB, levB = 0.0f;
    float bB_sv[8], bB_r0 = 0.0f;

    // ======================= INIT =======================
    if (wid == 0) {
        // launch period-0 y loads first (fly under init math)
        #pragma unroll
        for (int j = 0; j < 12; j++) {
            const int f = lane + 32 * j;
            const int row = f / 6, col = f % 6;
            cp16(smem_u32(ybuf[0]) + row * (YSTR * 4) + col * 16,
                 ybase + 32 + row * (NT * 4) + col * 16);
        }
        cp_commit();

        // per-series init: exps, gs cols 0..23, seed stile[1] cols 0..15 (pos 8..23)
        #pragma unroll
        for (int h = 0; h < 2; h++) {
            const int r = lane + 32 * h;
            const int s = s0 + r;
            const int idx = idxs[s];
            // reference derives BOTH smoothing params from lev_sms (its quirk)
            const float a = 1.0f / (1.0f + __expf(-lev_sms_p[idx]));
            const float* isr = init_seas_p + (size_t)idx * SEASK;
            float4* gsr = (float4*)(gs + (size_t)s * SEAW);
            float* sseed = stile[1] + r * TSTR;
            float svp[8], r0 = 0.0f;
            #pragma unroll
            for (int qd = 0; qd < 6; qd++) {
                const float4 x = *(const float4*)(isr + 4 * qd);
                float4 e;
                e.x = __expf(x.x); e.y = __expf(x.y); e.z = __expf(x.z); e.w = __expf(x.w);
                __stcs(gsr + qd, e);
                if (qd < 2) {
                    svp[4*qd+0] = e.x; svp[4*qd+1] = e.y;
                    svp[4*qd+2] = e.z; svp[4*qd+3] = e.w;
                    if (qd == 0) r0 = __expf(-x.x);
                } else {
                    *(float4*)(sseed + (qd - 2) * 4) = e;   // pos 8..23 -> cols 0..15
                }
            }
            if (h == 0) {
                aA = a; omaA = 1.0f - a; bA_r0 = r0;
                #pragma unroll
                for (int k = 0; k < 8; k++) bA_sv[k] = svp[k];
            } else {
                aB = a; omaB = 1.0f - a; bB_r0 = r0;
                #pragma unroll
                for (int k = 0; k < 8; k++) bB_sv[k] = svp[k];
            }
        }

        // ---- peel steps 0..7 for both series (y via direct LDG, one-time) ----
        #pragma unroll
        for (int h = 0; h < 2; h++) {
            const int r = lane + 32 * h;
            const int s = s0 + r;
            const float a   = (h == 0) ? aA : aB;
            const float oma = (h == 0) ? omaA : omaB;
            const float r0  = (h == 0) ? bA_r0 : bB_r0;
            float* svp      = (h == 0) ? bA_sv : bB_sv;

            const float4 v0 = ((const float4*)(y + (size_t)s * NT))[0];
            const float4 v1 = ((const float4*)(y + (size_t)s * NT))[1];
            float yt[8] = {v0.x, v0.y, v0.z, v0.w, v1.x, v1.y, v1.z, v1.w};
            float q_[8], nl_[8], dt_[8], ns_[8];

            float lev = yt[0] * r0;
            float llev = __logf(lev);
            nl_[0] = lev; dt_[0] = 0.0f;
            #pragma unroll
            for (int k = 1; k < 8; k++) q_[k] = a * __fdividef(yt[k], svp[k]);
            #pragma unroll
            for (int k = 1; k < 8; k++) { nl_[k] = fmaf(oma, lev, q_[k]); lev = nl_[k]; }
            #pragma unroll
            for (int k = 1; k < 8; k++)
                ns_[k] = fmaf(a, __fdividef(yt[k], nl_[k]), oma * svp[k]);
            #pragma unroll
            for (int k = 1; k < 8; k++) {
                const float ll = __logf(nl_[k]);
                dt_[k] = ll - llev; llev = ll;
            }
            llevb[r] = llev;
            if (h == 0) levA = lev; else levB = lev;

            // seed stile[1] cols 16..23 (pos 0 = init value, pos 1..7 = peel out)
            float* sseed = stile[1] + r * TSTR + 16;
            *(float4*)(sseed)     = make_float4(svp[0], ns_[1], ns_[2], ns_[3]);
            *(float4*)(sseed + 4) = make_float4(ns_[4], ns_[5], ns_[6], ns_[7]);

            // stage peel outputs: dtile row = {l0..7 | s0..7 | d0..7}
            float* pb = dtile + r * DSTR;
            *(float4*)(pb +  0) = make_float4(nl_[0], nl_[1], nl_[2], nl_[3]);
            *(float4*)(pb +  4) = make_float4(nl_[4], nl_[5], nl_[6], nl_[7]);
            *(float4*)(pb +  8) = make_float4(svp[0], ns_[1], ns_[2], ns_[3]);
            *(float4*)(pb + 12) = make_float4(ns_[4], ns_[5], ns_[6], ns_[7]);
            *(float4*)(pb + 16) = make_float4(dt_[0], dt_[1], dt_[2], dt_[3]);
            *(float4*)(pb + 20) = make_float4(dt_[4], dt_[5], dt_[6], dt_[7]);
        }
        __syncwarp();

        // coalesced peel writeback: levels 0..7, seas 24..31, logd 0..6 (64 rows)
        #pragma unroll
        for (int j = 0; j < 4; j++) {
            const int f = lane + 32 * j;
            const int row = f >> 1, qd = f & 1;
            __stcs((float4*)(gl + (size_t)(s0 + row) * LEVW) + qd,
                   ((const float4*)(dtile + row * DSTR))[qd]);
            __stcs((float4*)(gs + (size_t)(s0 + row) * SEAW + SEASK) + qd,
                   ((const float4*)(dtile + row * DSTR + 8))[qd]);
        }
        #pragma unroll
        for (int j = 0; j < 14; j++) {
            const int i = lane + 32 * j;
            const int row = i / 7, k = i % 7;
            __stcs(gd + (size_t)(s0 + row) * LOGW + k, dtile[row * DSTR + 17 + k]);
        }
        __syncwarp();
    }
    __syncthreads();   // B_init: seeds + llevb + ybuf[0] group committed

    // ============ iterations: W0 computes period p; W1 IO for period p-1 ============
    #pragma unroll 1
    for (int iter = 0; iter <= NPER; iter++) {
        if (wid == 0) {
            if (iter < NPER) {
                // prefetch y for period iter+1, then wait for period iter's group
                if (iter + 1 < NPER) {
                    const char* yb = ybase + 32 + (size_t)(iter + 1) * 96;
                    const unsigned d = smem_u32(ybuf[(iter + 1) & 1]);
                    #pragma unroll
                    for (int j = 0; j < 12; j++) {
                        const int f = lane + 32 * j;
                        const int row = f / 6, col = f % 6;
                        cp16(d + row * (YSTR * 4) + col * 16, yb + row * (NT * 4) + col * 16);
                    }
                    cp_commit();
                    cp_wait<1>();
                } else {
                    cp_wait<0>();
                }
                __syncwarp();

                const int b  = iter & 1;
                const int br = b ^ 1;
                const int rA = lane, rB = lane + 32;
                const float* ysmA  = ybuf[b]  + rA * YSTR;
                const float* ysmB  = ybuf[b]  + rB * YSTR;
                const float* soldA = stile[br] + rA * TSTR;
                const float* soldB = stile[br] + rB * TSTR;
                float* lnewA = ltile[b] + rA * TSTR;
                float* lnewB = ltile[b] + rB * TSTR;
                float* snewA = stile[b] + rA * TSTR;
                float* snewB = stile[b] + rB * TSTR;

                // interleave two independent recurrences (A/B) for ILP
                half12(ysmA,      soldA,      lnewA,      snewA,      aA, omaA, levA);
                half12(ysmB,      soldB,      lnewB,      snewB,      aB, omaB, levB);
                half12(ysmA + 12, soldA + 12, lnewA + 12, snewA + 12, aA, omaA, levA);
                half12(ysmB + 12, soldB + 12, lnewB + 12, snewB + 12, aB, omaB, levB);
            }
        } else if (iter >= 1) {
            const int P  = iter - 1;
            const int b  = P & 1;
            const int tp = 8 + 24 * P;

            if (lane == 0) {
                fence_async_shared();
                tma_store2d(&tml, tp,         s0, smem_u32(ltile[b]));
                tma_store2d(&tms, tp + SEASK, s0, smem_u32(stile[b]));
                bulk_commit();
            }

            // logs + diffs for both rows of this lane
            #pragma unroll
            for (int h = 0; h < 2; h++) {
                const int r = lane + 32 * h;
                float llev = llevb[r];
                const float* nlrow = ltile[b] + r * TSTR;
                float* db = dtile + r * DSTR;
                #pragma unroll
                for (int m = 0; m < 6; m++) {
                    const float4 v = *(const float4*)(nlrow + 4 * m);
                    const float l0 = __logf(v.x), l1 = __logf(v.y);
                    const float l2 = __logf(v.z), l3 = __logf(v.w);
                    *(float4*)(db + 4 * m) = make_float4(l0 - llev, l1 - l0, l2 - l1, l3 - l2);
                    llev = l3;
                }
                llevb[r] = llev;
            }
            __syncwarp();

            // gd: coalesced scalar streaming stores (64 rows x 24 cols)
            #pragma unroll
            for (int j = 0; j < 48; j++) {
                const int i = lane + 32 * j;
                const int row = i / 24, k = i % 24;
                __stcs(gd + (size_t)(s0 + row) * LOGW + tp - 1 + k, dtile[row * DSTR + k]);
            }

            if (lane == 0) bulk_wait<0>();   // tiles[b] drained before reuse at iter+1
        }
        __syncthreads();
    }
}

extern "C" void kernel_launch(void* const* d_in, const int* in_sizes, int n_in,
                              void* d_out, int out_size)
{
    const float* y         = (const float*)d_in[0];
    const int*   idxs      = (const int*)  d_in[1];
    const float* lev_sms   = (const float*)d_in[2];
    const float* init_seas = (const float*)d_in[4];  // d_in[3] unused (reference quirk)
    float* out = (float*)d_out;

    typedef CUresult (*EncodeFn)(CUtensorMap*, CUtensorMapDataType, cuuint32_t, void*,
                                 const cuuint64_t*, const cuuint64_t*, const cuuint32_t*,
                                 const cuuint32_t*, CUtensorMapInterleave, CUtensorMapSwizzle,
                                 CUtensorMapL2promotion, CUtensorMapFloatOOBfill);
    EncodeFn enc = nullptr;
    cudaDriverEntryPointQueryResult qr;
    cudaGetDriverEntryPointByVersion("cuTensorMapEncodeTiled", (void**)&enc, 12000,
                                     cudaEnableDefault, &qr);

    CUtensorMap tml, tms;
    {
        cuuint64_t dims[2]    = { (cuuint64_t)LEVW, (cuuint64_t)NS };
        cuuint64_t strides[1] = { (cuuint64_t)LEVW * 4 };
        cuuint32_t box[2]     = { 24, 64 };
        cuuint32_t es[2]      = { 1, 1 };
        enc(&tml, CU_TENSOR_MAP_DATA_TYPE_FLOAT32, 2, out, dims, strides, box, es,
            CU_TENSOR_MAP_INTERLEAVE_NONE, CU_TENSOR_MAP_SWIZZLE_NONE,
            CU_TENSOR_MAP_L2_PROMOTION_L2_128B, CU_TENSOR_MAP_FLOAT_OOB_FILL_NONE);
    }
    {
        float* gsp = out + (size_t)NS * LEVW;
        cuuint64_t dims[2]    = { (cuuint64_t)SEAW, (cuuint64_t)NS };
        cuuint64_t strides[1] = { (cuuint64_t)SEAW * 4 };
        cuuint32_t box[2]     = { 24, 64 };
        cuuint32_t es[2]      = { 1, 1 };
        enc(&tms, CU_TENSOR_MAP_DATA_TYPE_FLOAT32, 2, gsp, dims, strides, box, es,
            CU_TENSOR_MAP_INTERLEAVE_NONE, CU_TENSOR_MAP_SWIZZLE_NONE,
            CU_TENSOR_MAP_L2_PROMOTION_L2_128B, CU_TENSOR_MAP_FLOAT_OOB_FILL_NONE);
    }

    es_fwd_kernel<<<NS / NSER, BLOCK>>>(tml, tms, y, idxs, lev_sms, init_seas, out);
}

// round 16
// speedup vs baseline: 1.2290x; 1.0215x over previous
#include <cuda_runtime.h>
#include <cuda.h>

#define NS      32768
#define NT      512
#define SEASK   24
#define LEVW    512
#define SEAW    536
#define LOGW    511

#define NSER    64          // series per block (2 per compute lane)
#define BLOCK   96          // W0 compute | W1 IO rows 0-31 | W2 IO rows 32-63
#define NPER    21          // periods of 24 steps, t = 8..511
#define YSTR    28          // y smem row stride
#define TSTR    24          // tile row stride (TMA packed)
#define DSTR    28          // dtile row stride

__device__ __forceinline__ unsigned smem_u32(const void* p) {
    return (unsigned)__cvta_generic_to_shared(p);
}
__device__ __forceinline__ void cp16(unsigned dst, const void* src) {
    asm volatile("cp.async.cg.shared.global [%0], [%1], 16;\n" :: "r"(dst), "l"(src) : "memory");
}
__device__ __forceinline__ void cp_commit() {
    asm volatile("cp.async.commit_group;\n" ::: "memory");
}
template<int N> __device__ __forceinline__ void cp_wait() {
    asm volatile("cp.async.wait_group %0;\n" :: "n"(N) : "memory");
}
__device__ __forceinline__ void tma_store2d(const void* map, int x, int y, unsigned smem) {
    asm volatile("cp.async.bulk.tensor.2d.global.shared::cta.tile.bulk_group [%0, {%1, %2}], [%3];"
                 :: "l"(map), "r"(x), "r"(y), "r"(smem) : "memory");
}
__device__ __forceinline__ void bulk_commit() {
    asm volatile("cp.async.bulk.commit_group;" ::: "memory");
}
template<int N> __device__ __forceinline__ void bulk_wait() {
    asm volatile("cp.async.bulk.wait_group %0;" :: "n"(N) : "memory");
}
__device__ __forceinline__ void fence_async_shared() {
    asm volatile("fence.proxy.async.shared::cta;" ::: "memory");
}

// 12 recurrence steps, register-lean: only q/nl[12]+lev live across phases;
// y and sold are re-read from smem in the epilogue. sold col k = seasonal
// value of slot (8+k)%24 as of the previous period (24 steps old -> matches ref).
__device__ __forceinline__ void half12(
    const float* __restrict__ ysm, const float* __restrict__ sold,
    float* __restrict__ lnew, float* __restrict__ snew,
    float a, float oma, float& lev)
{
    float q[12], nl[12];
    #pragma unroll
    for (int m = 0; m < 3; m++) {
        const float4 v = *(const float4*)(ysm  + 4 * m);
        const float4 w = *(const float4*)(sold + 4 * m);
        q[4*m+0] = a * __fdividef(v.x, w.x);
        q[4*m+1] = a * __fdividef(v.y, w.y);
        q[4*m+2] = a * __fdividef(v.z, w.z);
        q[4*m+3] = a * __fdividef(v.w, w.w);
    }
    #pragma unroll
    for (int k = 0; k < 12; k++) { nl[k] = fmaf(oma, lev, q[k]); lev = nl[k]; }
    #pragma unroll
    for (int m = 0; m < 3; m++) {
        const float4 v = *(const float4*)(ysm  + 4 * m);   // reload (regs > LDS)
        const float4 w = *(const float4*)(sold + 4 * m);
        const float n0 = fmaf(a, __fdividef(v.x, nl[4*m+0]), oma * w.x);
        const float n1 = fmaf(a, __fdividef(v.y, nl[4*m+1]), oma * w.y);
        const float n2 = fmaf(a, __fdividef(v.z, nl[4*m+2]), oma * w.z);
        const float n3 = fmaf(a, __fdividef(v.w, nl[4*m+3]), oma * w.w);
        *(float4*)(snew + 4*m) = make_float4(n0, n1, n2, n3);
        *(float4*)(lnew + 4*m) = make_float4(nl[4*m+0], nl[4*m+1], nl[4*m+2], nl[4*m+3]);
    }
}

__global__ __launch_bounds__(BLOCK, 4) void es_fwd_kernel(
    const __grid_constant__ CUtensorMap tml,
    const __grid_constant__ CUtensorMap tms,
    const float* __restrict__ y,
    const int*   __restrict__ idxs,
    const float* __restrict__ lev_sms_p,
    const float* __restrict__ init_seas_p,
    float* __restrict__ out)
{
    __shared__ __align__(16) float ybuf[2][NSER * YSTR];   // 14336
    __shared__ __align__(16) float ltile[2][NSER * TSTR];  // 12288
    __shared__ __align__(16) float stile[2][NSER * TSTR];  // 12288 (state carry + TMA src)
    __shared__ __align__(16) float dtile[NSER * DSTR];     // 7168 (IO scratch + peel staging)
    __shared__ float llevb[NSER];

    const int tid  = threadIdx.x;
    const int wid  = tid / 32;
    const int lane = tid & 31;
    const int s0   = blockIdx.x * NSER;

    float* gl = out;
    float* gs = out + (size_t)NS * LEVW;
    float* gd = gs  + (size_t)NS * SEAW;
    const char* ybase = (const char*)(y + (size_t)s0 * NT);

    float aA = 0.f, omaA = 0.f, levA = 0.0f;
    float aB = 0.f, omaB = 0.f, levB = 0.0f;

    // ======================= INIT =======================
    if (wid == 0) {
        // period-0 y loads first (fly under init math)
        #pragma unroll
        for (int j = 0; j < 12; j++) {
            const int f = lane + 32 * j;
            const int row = f / 6, col = f % 6;
            cp16(smem_u32(ybuf[0]) + row * (YSTR * 4) + col * 16,
                 ybase + 32 + row * (NT * 4) + col * 16);
        }
        cp_commit();

        // per-series peel state (pos 0..7) + gs cols 0..7 + peel steps 0..7
        #pragma unroll
        for (int h = 0; h < 2; h++) {
            const int r = lane + 32 * h;
            const int s = s0 + r;
            const int idx = idxs[s];
            // reference derives BOTH smoothing params from lev_sms (its quirk)
            const float a   = 1.0f / (1.0f + __expf(-lev_sms_p[idx]));
            const float oma = 1.0f - a;
            const float* isr = init_seas_p + (size_t)idx * SEASK;

            const float4 x0 = *(const float4*)(isr + 0);
            const float4 x1 = *(const float4*)(isr + 4);
            float4 e0, e1;
            e0.x = __expf(x0.x); e0.y = __expf(x0.y); e0.z = __expf(x0.z); e0.w = __expf(x0.w);
            e1.x = __expf(x1.x); e1.y = __expf(x1.y); e1.z = __expf(x1.z); e1.w = __expf(x1.w);
            float svp[8] = {e0.x, e0.y, e0.z, e0.w, e1.x, e1.y, e1.z, e1.w};
            const float r0 = __expf(-x0.x);
            float4* gsr = (float4*)(gs + (size_t)s * SEAW);
            __stcs(gsr + 0, e0); __stcs(gsr + 1, e1);

            // ---- peel steps 0..7 (direct LDG, one-time) ----
            const float4 v0 = ((const float4*)(y + (size_t)s * NT))[0];
            const float4 v1 = ((const float4*)(y + (size_t)s * NT))[1];
            float yt[8] = {v0.x, v0.y, v0.z, v0.w, v1.x, v1.y, v1.z, v1.w};
            float q_[8], nl_[8], dt_[8], ns_[8];

            float lev = yt[0] * r0;
            float llev = __logf(lev);
            nl_[0] = lev; dt_[0] = 0.0f;
            #pragma unroll
            for (int k = 1; k < 8; k++) q_[k] = a * __fdividef(yt[k], svp[k]);
            #pragma unroll
            for (int k = 1; k < 8; k++) { nl_[k] = fmaf(oma, lev, q_[k]); lev = nl_[k]; }
            #pragma unroll
            for (int k = 1; k < 8; k++)
                ns_[k] = fmaf(a, __fdividef(yt[k], nl_[k]), oma * svp[k]);
            #pragma unroll
            for (int k = 1; k < 8; k++) {
                const float ll = __logf(nl_[k]);
                dt_[k] = ll - llev; llev = ll;
            }
            llevb[r] = llev;
            if (h == 0) { aA = a; omaA = oma; levA = lev; }
            else        { aB = a; omaB = oma; levB = lev; }

            // seed stile[1] cols 16..23 (pos 0 = init value, pos 1..7 = peel out)
            float* sseed = stile[1] + r * TSTR + 16;
            *(float4*)(sseed)     = make_float4(svp[0], ns_[1], ns_[2], ns_[3]);
            *(float4*)(sseed + 4) = make_float4(ns_[4], ns_[5], ns_[6], ns_[7]);

            // stage peel outputs: dtile row = {l0..7 | s0..7 | d0..7}
            float* pb = dtile + r * DSTR;
            *(float4*)(pb +  0) = make_float4(nl_[0], nl_[1], nl_[2], nl_[3]);
            *(float4*)(pb +  4) = make_float4(nl_[4], nl_[5], nl_[6], nl_[7]);
            *(float4*)(pb +  8) = make_float4(svp[0], ns_[1], ns_[2], ns_[3]);
            *(float4*)(pb + 12) = make_float4(ns_[4], ns_[5], ns_[6], ns_[7]);
            *(float4*)(pb + 16) = make_float4(dt_[0], dt_[1], dt_[2], dt_[3]);
            *(float4*)(pb + 20) = make_float4(dt_[4], dt_[5], dt_[6], dt_[7]);
        }
        __syncwarp();

        // coalesced peel writeback: levels 0..7, seas 24..31, logd 0..6 (64 rows)
        #pragma unroll
        for (int j = 0; j < 4; j++) {
            const int f = lane + 32 * j;
            const int row = f >> 1, qd = f & 1;
            __stcs((float4*)(gl + (size_t)(s0 + row) * LEVW) + qd,
                   ((const float4*)(dtile + row * DSTR))[qd]);
            __stcs((float4*)(gs + (size_t)(s0 + row) * SEAW + SEASK) + qd,
                   ((const float4*)(dtile + row * DSTR + 8))[qd]);
        }
        #pragma unroll
        for (int j = 0; j < 14; j++) {
            const int i = lane + 32 * j;
            const int row = i / 7, k = i % 7;
            __stcs(gd + (size_t)(s0 + row) * LOGW + k, dtile[row * DSTR + 17 + k]);
        }
        __syncwarp();
    } else {
        // W1: rows 0..31, W2: rows 32..63 — gs cols 8..23 + stile[1] seeds cols 0..15
        const int r = (wid - 1) * 32 + lane;
        const int s = s0 + r;
        const int idx = idxs[s];
        const float* isr = init_seas_p + (size_t)idx * SEASK;
        float* sseed = stile[1] + r * TSTR;
        float4* gsr = (float4*)(gs + (size_t)s * SEAW);
        #pragma unroll
        for (int qd = 2; qd < 6; qd++) {
            const float4 x = *(const float4*)(isr + 4 * qd);
            float4 e;
            e.x = __expf(x.x); e.y = __expf(x.y); e.z = __expf(x.z); e.w = __expf(x.w);
            __stcs(gsr + qd, e);
            *(float4*)(sseed + (qd - 2) * 4) = e;   // pos 8..23 -> cols 0..15
        }
    }
    __syncthreads();   // B_init: seeds + llevb + ybuf[0] group committed

    // ============ iter p: W0 computes period p; W1/W2 IO for period p-1 ============
    #pragma unroll 1
    for (int iter = 0; iter <= NPER; iter++) {
        if (wid == 0) {
            if (iter < NPER) {
                if (iter + 1 < NPER) {
                    const char* yb = ybase + 32 + (size_t)(iter + 1) * 96;
                    const unsigned d = smem_u32(ybuf[(iter + 1) & 1]);
                    #pragma unroll
                    for (int j = 0; j < 12; j++) {
                        const int f = lane + 32 * j;
                        const int row = f / 6, col = f % 6;
                        cp16(d + row * (YSTR * 4) + col * 16, yb + row * (NT * 4) + col * 16);
                    }
                    cp_commit();
                    cp_wait<1>();
                } else {
                    cp_wait<0>();
                }
                __syncwarp();

                const int b  = iter & 1;
                const int br = b ^ 1;
                const int rA = lane, rB = lane + 32;
                // interleave two independent recurrences (A/B) for ILP;
                // lean half12 keeps only ~14 floats live per call
                half12(ybuf[b] + rA*YSTR,      stile[br] + rA*TSTR,
                       ltile[b] + rA*TSTR,     stile[b] + rA*TSTR,      aA, omaA, levA);
                half12(ybuf[b] + rB*YSTR,      stile[br] + rB*TSTR,
                       ltile[b] + rB*TSTR,     stile[b] + rB*TSTR,      aB, omaB, levB);
                half12(ybuf[b] + rA*YSTR + 12, stile[br] + rA*TSTR + 12,
                       ltile[b] + rA*TSTR + 12, stile[b] + rA*TSTR + 12, aA, omaA, levA);
                half12(ybuf[b] + rB*YSTR + 12, stile[br] + rB*TSTR + 12,
                       ltile[b] + rB*TSTR + 12, stile[b] + rB*TSTR + 12, aB, omaB, levB);
            }
        } else if (iter >= 1) {
            const int P  = iter - 1;
            const int b  = P & 1;
            const int tp = 8 + 24 * P;
            const int rbase = (wid - 1) * 32;
            const int r = rbase + lane;

            if (wid == 1 && lane == 0) {
                fence_async_shared();
                tma_store2d(&tml, tp,         s0, smem_u32(ltile[b]));
                tma_store2d(&tms, tp + SEASK, s0, smem_u32(stile[b]));
                bulk_commit();
            }

            // logs + diffs for my row
            {
                float llev = llevb[r];
                const float* nlrow = ltile[b] + r * TSTR;
                float* db = dtile + r * DSTR;
                #pragma unroll
                for (int m = 0; m < 6; m++) {
                    const float4 v = *(const float4*)(nlrow + 4 * m);
                    const float l0 = __logf(v.x), l1 = __logf(v.y);
                    const float l2 = __logf(v.z), l3 = __logf(v.w);
                    *(float4*)(db + 4 * m) = make_float4(l0 - llev, l1 - l0, l2 - l1, l3 - l2);
                    llev = l3;
                }
                llevb[r] = llev;
            }
            __syncwarp();

            // gd: my 32 rows x 24 cols, coalesced scalar streaming stores
            #pragma unroll
            for (int j = 0; j < 24; j++) {
                const int i = lane + 32 * j;
                const int row = rbase + i / 24, k = i % 24;
                __stcs(gd + (size_t)(s0 + row) * LOGW + tp - 1 + k, dtile[row * DSTR + k]);
            }

            if (wid == 1 && lane == 0) bulk_wait<0>();   // tiles[b] drained before reuse
        }
        __syncthreads();
    }
}

extern "C" void kernel_launch(void* const* d_in, const int* in_sizes, int n_in,
                              void* d_out, int out_size)
{
    const float* y         = (const float*)d_in[0];
    const int*   idxs      = (const int*)  d_in[1];
    const float* lev_sms   = (const float*)d_in[2];
    const float* init_seas = (const float*)d_in[4];  // d_in[3] unused (reference quirk)
    float* out = (float*)d_out;

    typedef CUresult (*EncodeFn)(CUtensorMap*, CUtensorMapDataType, cuuint32_t, void*,
                                 const cuuint64_t*, const cuuint64_t*, const cuuint32_t*,
                                 const cuuint32_t*, CUtensorMapInterleave, CUtensorMapSwizzle,
                                 CUtensorMapL2promotion, CUtensorMapFloatOOBfill);
    EncodeFn enc = nullptr;
    cudaDriverEntryPointQueryResult qr;
    cudaGetDriverEntryPointByVersion("cuTensorMapEncodeTiled", (void**)&enc, 12000,
                                     cudaEnableDefault, &qr);

    CUtensorMap tml, tms;
    {
        cuuint64_t dims[2]    = { (cuuint64_t)LEVW, (cuuint64_t)NS };
        cuuint64_t strides[1] = { (cuuint64_t)LEVW * 4 };
        cuuint32_t box[2]     = { 24, 64 };
        cuuint32_t es[2]      = { 1, 1 };
        enc(&tml, CU_TENSOR_MAP_DATA_TYPE_FLOAT32, 2, out, dims, strides, box, es,
            CU_TENSOR_MAP_INTERLEAVE_NONE, CU_TENSOR_MAP_SWIZZLE_NONE,
            CU_TENSOR_MAP_L2_PROMOTION_L2_128B, CU_TENSOR_MAP_FLOAT_OOB_FILL_NONE);
    }
    {
        float* gsp = out + (size_t)NS * LEVW;
        cuuint64_t dims[2]    = { (cuuint64_t)SEAW, (cuuint64_t)NS };
        cuuint64_t strides[1] = { (cuuint64_t)SEAW * 4 };
        cuuint32_t box[2]     = { 24, 64 };
        cuuint32_t es[2]      = { 1, 1 };
        enc(&tms, CU_TENSOR_MAP_DATA_TYPE_FLOAT32, 2, gsp, dims, strides, box, es,
            CU_TENSOR_MAP_INTERLEAVE_NONE, CU_TENSOR_MAP_SWIZZLE_NONE,
            CU_TENSOR_MAP_L2_PROMOTION_L2_128B, CU_TENSOR_MAP_FLOAT_OOB_FILL_NONE);
    }

    es_fwd_kernel<<<NS / NSER, BLOCK>>>(tml, tms, y, idxs, lev_sms, init_seas, out);
}